// round 1
// baseline (speedup 1.0000x reference)
#include <cuda_runtime.h>
#include <cstdint>

#define DIMC 768
#define HEADS 12
#define NTOK 64
#define DH 64

// ---------------- scratch (device globals; no allocation allowed) ----------------
__device__ float g_q[65536 * 768];
__device__ float g_k[65536 * 768];
__device__ float g_v[65536 * 768];
__device__ float g_c[65536 * 768];
__device__ float g_tbl[343 * 12];
__device__ float g_bias[12 * 64 * 64];

// ---------------- helpers ----------------
__device__ __forceinline__ void cp_async16(void* s, const void* g) {
    uint32_t sa = (uint32_t)__cvta_generic_to_shared(s);
    asm volatile("cp.async.cg.shared.global [%0], [%1], 16;\n" ::"r"(sa), "l"(g) : "memory");
}
__device__ __forceinline__ void cp_commit() { asm volatile("cp.async.commit_group;\n" ::: "memory"); }
__device__ __forceinline__ void cp_wait0() { asm volatile("cp.async.wait_group 0;\n" ::: "memory"); }

__device__ __forceinline__ uint32_t f2tf32(float f) {
    uint32_t r;
    asm("cvt.rna.tf32.f32 %0, %1;" : "=r"(r) : "f"(f));
    return r;
}

__device__ __forceinline__ void mma_tf32(float* c, const uint32_t* a, const uint32_t* b) {
    asm volatile(
        "mma.sync.aligned.m16n8k8.row.col.f32.tf32.tf32.f32 "
        "{%0,%1,%2,%3},{%4,%5,%6,%7},{%8,%9},{%0,%1,%2,%3};"
        : "+f"(c[0]), "+f"(c[1]), "+f"(c[2]), "+f"(c[3])
        : "r"(a[0]), "r"(a[1]), "r"(a[2]), "r"(a[3]), "r"(b[0]), "r"(b[1]));
}

// ---------------- TF32 GEMM: C[M,768] = A[M,768] @ B[768,768] (+bias) ----------------
// CTA tile 128x128, K tile 32, 8 warps (2x4), warp tile 64x32, double-buffered cp.async.
#define TILE_M 128
#define TILE_N 128
#define TILE_K 32
#define AS_STRIDE 36   // (m*4+k)%32 unique -> conflict free frag loads
#define BS_STRIDE 136  // (k*8+n)%32 unique -> conflict free frag loads
#define GEMM_SMEM ((2 * TILE_M * AS_STRIDE + 2 * TILE_K * BS_STRIDE) * 4)

__global__ void __launch_bounds__(256) gemm_tf32_kernel(
    const float* __restrict__ A, const float* __restrict__ B,
    const float* __restrict__ bias, float* __restrict__ C) {
    extern __shared__ float smem[];
    float* As = smem;                            // 2 x 128*36
    float* Bs = smem + 2 * TILE_M * AS_STRIDE;   // 2 x 32*136

    const int tid = threadIdx.x;
    const int bm = blockIdx.y, bn = blockIdx.x;
    const int lane = tid & 31, warp = tid >> 5;
    const int wm = (warp & 1) * 64, wn = (warp >> 1) * 32;

    // load mapping
    const int ar = tid >> 3;          // 0..31 (row within a 32-row pass)
    const int ac = (tid & 7) * 4;     // col (floats)
    const int br = tid >> 5;          // 0..7
    const int bc = (tid & 31) * 4;    // 0..124

    const float* Ag = A + (size_t)(bm * TILE_M) * DIMC;
    const float* Bg = B + bn * TILE_N;

    float acc[4][4][4];
#pragma unroll
    for (int i = 0; i < 4; i++)
#pragma unroll
        for (int j = 0; j < 4; j++)
#pragma unroll
            for (int k = 0; k < 4; k++) acc[i][j][k] = 0.f;

    const int NK = DIMC / TILE_K;  // 24

    // stage loader
    auto load_stage = [&](int kt, int s) {
        float* as = As + s * TILE_M * AS_STRIDE;
        float* bs = Bs + s * TILE_K * BS_STRIDE;
        const float* ag = Ag + kt * TILE_K;
#pragma unroll
        for (int p = 0; p < 4; p++) {
            int r = p * 32 + ar;
            cp_async16(as + r * AS_STRIDE + ac, ag + (size_t)r * DIMC + ac);
        }
        const float* bg = Bg + (size_t)(kt * TILE_K) * DIMC;
#pragma unroll
        for (int p = 0; p < 4; p++) {
            int r = p * 8 + br;
            cp_async16(bs + r * BS_STRIDE + bc, bg + (size_t)r * DIMC + bc);
        }
        cp_commit();
    };

    load_stage(0, 0);

    for (int kt = 0; kt < NK; kt++) {
        const int s = kt & 1;
        cp_wait0();
        __syncthreads();
        if (kt + 1 < NK) load_stage(kt + 1, s ^ 1);

        const float* as = As + s * TILE_M * AS_STRIDE;
        const float* bs = Bs + s * TILE_K * BS_STRIDE;
#pragma unroll
        for (int ks = 0; ks < 4; ks++) {
            const int k0 = ks * 8;
            uint32_t af[4][4], bf[4][2];
#pragma unroll
            for (int mt = 0; mt < 4; mt++) {
                const int rb = wm + mt * 16 + (lane >> 2);
                const int cc = k0 + (lane & 3);
                af[mt][0] = f2tf32(as[rb * AS_STRIDE + cc]);
                af[mt][1] = f2tf32(as[(rb + 8) * AS_STRIDE + cc]);
                af[mt][2] = f2tf32(as[rb * AS_STRIDE + cc + 4]);
                af[mt][3] = f2tf32(as[(rb + 8) * AS_STRIDE + cc + 4]);
            }
#pragma unroll
            for (int nt = 0; nt < 4; nt++) {
                const int cb = wn + nt * 8 + (lane >> 2);
                const int rr = k0 + (lane & 3);
                bf[nt][0] = f2tf32(bs[rr * BS_STRIDE + cb]);
                bf[nt][1] = f2tf32(bs[(rr + 4) * BS_STRIDE + cb]);
            }
#pragma unroll
            for (int mt = 0; mt < 4; mt++)
#pragma unroll
                for (int nt = 0; nt < 4; nt++) mma_tf32(acc[mt][nt], af[mt], bf[nt]);
        }
        __syncthreads();
    }

    // epilogue
#pragma unroll
    for (int mt = 0; mt < 4; mt++) {
#pragma unroll
        for (int nt = 0; nt < 4; nt++) {
            const int row = bm * TILE_M + wm + mt * 16 + (lane >> 2);
            const int col = bn * TILE_N + wn + nt * 8 + (lane & 3) * 2;
            const float b0 = bias ? bias[col] : 0.f;
            const float b1 = bias ? bias[col + 1] : 0.f;
            float2 v0 = make_float2(acc[mt][nt][0] + b0, acc[mt][nt][1] + b1);
            float2 v1 = make_float2(acc[mt][nt][2] + b0, acc[mt][nt][3] + b1);
            *(float2*)&C[(size_t)row * DIMC + col] = v0;
            *(float2*)&C[(size_t)(row + 8) * DIMC + col] = v1;
        }
    }
}

// ---------------- CPB MLP -> table (343 x 12) ----------------
__global__ void cpb_kernel(const float* __restrict__ tabl, const float* __restrict__ w1,
                           const float* __restrict__ b1, const float* __restrict__ w2,
                           const float* __restrict__ b2) {
    __shared__ float red[128 * 12];
    const int r = blockIdx.x;
    const int t = threadIdx.x;
    const float t0 = tabl[r * 3 + 0], t1 = tabl[r * 3 + 1], t2 = tabl[r * 3 + 2];
    float part[12];
#pragma unroll
    for (int hh = 0; hh < 12; hh++) part[hh] = 0.f;
    for (int j = t; j < 512; j += 128) {
        float h = t0 * w1[j] + t1 * w1[512 + j] + t2 * w1[1024 + j] + b1[j];
        h = fmaxf(h, 0.f);
#pragma unroll
        for (int hh = 0; hh < 12; hh++) part[hh] += h * w2[j * 12 + hh];
    }
#pragma unroll
    for (int hh = 0; hh < 12; hh++) red[t * 12 + hh] = part[hh];
    __syncthreads();
    if (t < 12) {
        float s = b2[t];
        for (int i = 0; i < 128; i++) s += red[i * 12 + t];
        g_tbl[r * 12 + t] = s;
    }
}

// ---------------- gather + 16*sigmoid -> g_bias[h][i*64+j] ----------------
__global__ void bias_kernel(const int* __restrict__ idx) {
    const int g = blockIdx.x * blockDim.x + threadIdx.x;
    if (g >= 12 * 4096) return;
    const int h = g / 4096, ij = g % 4096;
    const float x = g_tbl[idx[ij] * 12 + h];
    g_bias[g] = 16.f / (1.f + __expf(-x));
}

// ---------------- fused attention per (window, head) ----------------
// smem: qs[64*65] kT[64*65] vs[64*64] ps[64*65] qn[64] kn[64]
#define ATTN_SMEM ((64 * 65 * 3 + 64 * 64 + 128) * 4)

__global__ void __launch_bounds__(128) attn_kernel(
    const float* __restrict__ Q, const float* __restrict__ K,
    const float* __restrict__ V, const float* __restrict__ LS,
    float* __restrict__ O) {
    extern __shared__ float sm[];
    float* qs = sm;                 // [i*65+d]
    float* kT = qs + 64 * 65;       // [d*65+j]
    float* vs = kT + 64 * 65;       // [j*64+d]
    float* ps = vs + 64 * 64;       // [i*65+j]
    float* qn = ps + 64 * 65;
    float* kn = qn + 64;

    const int b = blockIdx.x, h = blockIdx.y;
    const int t = threadIdx.x;
    const size_t base = ((size_t)b * NTOK) * DIMC + h * DH;

    for (int idx = t; idx < 4096; idx += 128) {
        const int r = idx >> 6, d = idx & 63;
        const size_t off = base + (size_t)r * DIMC + d;
        qs[r * 65 + d] = Q[off];
        kT[d * 65 + r] = K[off];
        vs[r * 64 + d] = V[off];
    }
    __syncthreads();

    if (t < 64) {
        float s = 0.f;
#pragma unroll 8
        for (int d = 0; d < 64; d++) { float x = qs[t * 65 + d]; s += x * x; }
        qn[t] = sqrtf(s);
    } else {
        const int j = t - 64;
        float s = 0.f;
#pragma unroll 8
        for (int d = 0; d < 64; d++) { float x = kT[d * 65 + j]; s += x * x; }
        kn[j] = sqrtf(s);
    }
    __syncthreads();

    const float scale = fmaxf(LS[h], 0.01f);
    const float* bg = g_bias + h * 4096;

    // S = q@k^T / denom * scale + bias16 ; each thread computes a 4x8 tile
    {
        const int ti = t >> 3, tj = t & 7;
        const int i0 = ti * 4, j0 = tj * 8;
        float acc[4][8];
#pragma unroll
        for (int ii = 0; ii < 4; ii++)
#pragma unroll
            for (int jj = 0; jj < 8; jj++) acc[ii][jj] = 0.f;
#pragma unroll 4
        for (int d = 0; d < 64; d++) {
            float qv[4], kv[8];
#pragma unroll
            for (int ii = 0; ii < 4; ii++) qv[ii] = qs[(i0 + ii) * 65 + d];
#pragma unroll
            for (int jj = 0; jj < 8; jj++) kv[jj] = kT[d * 65 + j0 + jj];
#pragma unroll
            for (int ii = 0; ii < 4; ii++)
#pragma unroll
                for (int jj = 0; jj < 8; jj++) acc[ii][jj] += qv[ii] * kv[jj];
        }
#pragma unroll
        for (int ii = 0; ii < 4; ii++)
#pragma unroll
            for (int jj = 0; jj < 8; jj++) {
                const int i = i0 + ii, j = j0 + jj;
                const float den = fmaxf(qn[i] * kn[j], 1e-6f);
                ps[i * 65 + j] = acc[ii][jj] / den * scale + bg[i * 64 + j];
            }
    }
    __syncthreads();

    // softmax rows
    if (t < 64) {
        float m = -1e30f;
#pragma unroll 8
        for (int j = 0; j < 64; j++) m = fmaxf(m, ps[t * 65 + j]);
        float s = 0.f;
#pragma unroll 8
        for (int j = 0; j < 64; j++) {
            const float e = __expf(ps[t * 65 + j] - m);
            ps[t * 65 + j] = e;
            s += e;
        }
        const float inv = 1.f / s;
#pragma unroll 8
        for (int j = 0; j < 64; j++) ps[t * 65 + j] *= inv;
    }
    __syncthreads();

    // O = P @ V ; 4x8 tile per thread over (i, d)
    {
        const int ti = t >> 3, tj = t & 7;
        const int i0 = ti * 4, d0 = tj * 8;
        float acc[4][8];
#pragma unroll
        for (int ii = 0; ii < 4; ii++)
#pragma unroll
            for (int dd = 0; dd < 8; dd++) acc[ii][dd] = 0.f;
#pragma unroll 4
        for (int j = 0; j < 64; j++) {
            float pv[4], vv[8];
#pragma unroll
            for (int ii = 0; ii < 4; ii++) pv[ii] = ps[(i0 + ii) * 65 + j];
#pragma unroll
            for (int dd = 0; dd < 8; dd++) vv[dd] = vs[j * 64 + d0 + dd];
#pragma unroll
            for (int ii = 0; ii < 4; ii++)
#pragma unroll
                for (int dd = 0; dd < 8; dd++) acc[ii][dd] += pv[ii] * vv[dd];
        }
#pragma unroll
        for (int ii = 0; ii < 4; ii++)
#pragma unroll
            for (int dd = 0; dd < 8; dd++)
                O[base + (size_t)(i0 + ii) * DIMC + d0 + dd] = acc[ii][dd];
    }
}

// ---------------- launch ----------------
extern "C" void kernel_launch(void* const* d_in, const int* in_sizes, int n_in,
                              void* d_out, int out_size) {
    const float* x   = (const float*)d_in[0];
    const float* q_w = (const float*)d_in[1];
    const float* q_b = (const float*)d_in[2];
    const float* k_w = (const float*)d_in[3];
    const float* v_w = (const float*)d_in[4];
    const float* v_b = (const float*)d_in[5];
    const float* cw1 = (const float*)d_in[6];
    const float* cb1 = (const float*)d_in[7];
    const float* cw2 = (const float*)d_in[8];
    const float* cb2 = (const float*)d_in[9];
    const float* ls  = (const float*)d_in[10];
    const float* pw  = (const float*)d_in[11];
    const float* pb  = (const float*)d_in[12];
    const float* tab = (const float*)d_in[13];
    const int*   idx = (const int*)d_in[14];
    float* out = (float*)d_out;

    const int rows = in_sizes[0] / DIMC;  // 65536
    const int B = rows / NTOK;            // 1024

    float *dq, *dk, *dv, *dc;
    cudaGetSymbolAddress((void**)&dq, g_q);
    cudaGetSymbolAddress((void**)&dk, g_k);
    cudaGetSymbolAddress((void**)&dv, g_v);
    cudaGetSymbolAddress((void**)&dc, g_c);

    cudaFuncSetAttribute(gemm_tf32_kernel, cudaFuncAttributeMaxDynamicSharedMemorySize, GEMM_SMEM);
    cudaFuncSetAttribute(attn_kernel, cudaFuncAttributeMaxDynamicSharedMemorySize, ATTN_SMEM);

    cpb_kernel<<<343, 128>>>(tab, cw1, cb1, cw2, cb2);
    bias_kernel<<<(12 * 4096 + 255) / 256, 256>>>(idx);

    dim3 gg(DIMC / TILE_N, rows / TILE_M);
    gemm_tf32_kernel<<<gg, 256, GEMM_SMEM>>>(x, q_w, q_b, dq);
    gemm_tf32_kernel<<<gg, 256, GEMM_SMEM>>>(x, k_w, nullptr, dk);
    gemm_tf32_kernel<<<gg, 256, GEMM_SMEM>>>(x, v_w, v_b, dv);

    dim3 ga(B, HEADS);
    attn_kernel<<<ga, 128, ATTN_SMEM>>>(dq, dk, dv, ls, dc);

    gemm_tf32_kernel<<<gg, 256, GEMM_SMEM>>>(dc, pw, pb, out);
}